// round 17
// baseline (speedup 1.0000x reference)
#include <cuda_runtime.h>
#include <cuda_fp16.h>
#include <cstdint>

// Problem constants
#define B_SZ   2
#define L_SZ   4096
#define DMODEL 1024
#define DINT   64
#define KW     32
#define SUBH   5
#define HEADS  14
#define ML     (B_SZ * L_SZ)          // 8192 rows
#define NQK    320
#define NQKP   384                    // padded to 3*128
#define NV     896

// ---------------- scratch (static device globals; no allocation) -------------
__device__ __half g_qp[ML * NQKP];
__device__ __half g_kp[ML * NQKP];
__device__ __half g_vp[ML * NV];
__device__ __half g_sc[SUBH * B_SZ * L_SZ * KW];
__device__ __half g_oa[ML * NV];
__device__ __half g_wq[NQKP * DMODEL];
__device__ __half g_wk[NQKP * DMODEL];
__device__ __half g_wv[NV * DMODEL];
__device__ __half g_wc[DMODEL * NV];
__device__ float g_bqp[NQKP], g_bkp[NQKP];

// ---------------- helpers ------------------------------------------------
__device__ __forceinline__ uint32_t smem_u32(const void* p) {
    uint32_t a;
    asm("{ .reg .u64 t; cvta.to.shared.u64 t, %1; cvt.u32.u64 %0, t; }" : "=r"(a) : "l"(p));
    return a;
}
__device__ __forceinline__ void cpa16(uint32_t s, const void* g) {
    asm volatile("cp.async.cg.shared.global [%0], [%1], 16;" :: "r"(s), "l"(g));
}
#define CPA_COMMIT() asm volatile("cp.async.commit_group;" ::: "memory")
#define CPA_WAIT(n)  asm volatile("cp.async.wait_group %0;" :: "n"(n) : "memory")

#define LDSM4(r0, r1, r2, r3, a) \
    asm volatile("ldmatrix.sync.aligned.m8n8.x4.shared.b16 {%0,%1,%2,%3}, [%4];" \
        : "=r"(r0), "=r"(r1), "=r"(r2), "=r"(r3) : "r"(a))

#define MMAF16(c, a, b0, b1) \
    asm volatile("mma.sync.aligned.m16n8k16.row.col.f32.f16.f16.f32 " \
        "{%0,%1,%2,%3},{%4,%5,%6,%7},{%8,%9},{%0,%1,%2,%3};" \
        : "+f"((c)[0]), "+f"((c)[1]), "+f"((c)[2]), "+f"((c)[3]) \
        : "r"((a)[0]), "r"((a)[1]), "r"((a)[2]), "r"((a)[3]), "r"(b0), "r"(b1))

__device__ __forceinline__ uint32_t pack2(float a, float b) {
    __half2 h;
    h.x = __float2half_rn(a); h.y = __float2half_rn(b);
    return *(uint32_t*)&h;
}
#define STS128(so, h) \
    asm volatile("st.shared.v4.b32 [%0], {%1,%2,%3,%4};" \
        :: "r"(so), "r"((h).x), "r"((h).y), "r"((h).z), "r"((h).w) : "memory")

// ---------------- weight conversion kernel ------------------------------------
#define CONV_BLOCKS (2688 + 2)

__global__ __launch_bounds__(256)
void conv_w_all(const float* __restrict__ Wq, const float* __restrict__ Wk,
                const float* __restrict__ Wv, const float* __restrict__ Wc,
                const float* __restrict__ bq, const float* __restrict__ bk,
                __half* __restrict__ wq, __half* __restrict__ wk,
                __half* __restrict__ wv, __half* __restrict__ wc,
                float* __restrict__ bqp, float* __restrict__ bkp)
{
    const int wb = blockIdx.x, tid = threadIdx.x;
    if (wb >= 2688) {
        const float* src = (wb == 2688) ? bq : bk;
        float* dst = (wb == 2688) ? bqp : bkp;
        for (int i = tid; i < NQKP; i += 256) dst[i] = (i < NQK) ? src[i] : 0.f;
        return;
    }
    if (wb < 768) {
        const bool isq = (wb < 384);
        const float* W = isq ? Wq : Wk;
        __half* dst = isq ? wq : wk;
        int n = isq ? wb : (wb - 384);
        if (n >= NQK) {
            for (int kk = tid; kk < DMODEL; kk += 256) dst[(size_t)n * DMODEL + kk] = __float2half(0.f);
            return;
        }
        int head = n >> 6, i = n & 63;
        for (int kk = tid; kk < DMODEL; kk += 256)
            dst[(size_t)n * DMODEL + kk] = __float2half_rn(W[((size_t)head * DMODEL + kk) * 64 + i]);
    } else if (wb < 1664) {
        int n = wb - 768;
        int head = n >> 6, i = n & 63;
        for (int kk = tid; kk < DMODEL; kk += 256)
            wv[(size_t)n * DMODEL + kk] = __float2half_rn(Wv[((size_t)head * DMODEL + kk) * 64 + i]);
    } else {
        int n = wb - 1664;
        for (int kk = tid; kk < NV; kk += 256)
            wc[(size_t)n * NV + kk] = __float2half_rn(Wc[(size_t)kk * DMODEL + n]);
    }
}

// ---------------- fp16 HMMA GEMM, 128x128 tile, K-chunk 64 -------------------
#define APAD 72
#define A_OFF 0
#define B_OFF 9216
#define STE   18432
#define GEMM_SMEM (2 * STE * 2)

template <bool A32, bool OUT_HALF>
__device__ __forceinline__ void gemm_tile128(
    const void* __restrict__ Av, const __half* __restrict__ B,
    const float* __restrict__ bias, void* __restrict__ Cv,
    int m0, int n0, int N, int K, uint32_t sb)
{
    const int tid = threadIdx.x, lane = tid & 31, wid = tid >> 5;
    const int wm = wid >> 1, wn = wid & 1;

    float c[2][8][4];
    #pragma unroll
    for (int i = 0; i < 2; i++)
        #pragma unroll
        for (int j = 0; j < 8; j++)
            #pragma unroll
            for (int q = 0; q < 4; q++) c[i][j][q] = 0.f;

    const int ld_row0 = tid >> 3;
    const int ld_col  = (tid & 7) * 8;

    const int r = lane & 7, g = lane >> 3;
    const int a_ld_row = (g & 1) * 8 + r;
    const int a_ld_k   = (g >> 1) * 8;
    const int b_ld_row = (g >> 1) * 8 + r;
    const int b_ld_k   = (g & 1) * 8;

    const int nit = K >> 6;
    const __half* A16 = (const __half*)Av;
    const float*  Af  = (const float*)Av;

    float4 av[8];

    if (A32) {
        #pragma unroll
        for (int i = 0; i < 4; i++) {
            int row = ld_row0 + i * 32;
            const float* ap = Af + (size_t)(m0 + row) * K + ld_col;
            av[2 * i]     = *(const float4*)ap;
            av[2 * i + 1] = *(const float4*)(ap + 4);
        }
    }
    {
        uint32_t base = sb;
        #pragma unroll
        for (int i = 0; i < 4; i++) {
            int row = ld_row0 + i * 32;
            uint32_t so = base + (uint32_t)(row * APAD + ld_col) * 2;
            if (!A32)
                cpa16(so + A_OFF * 2, A16 + (size_t)(m0 + row) * K + ld_col);
            cpa16(so + B_OFF * 2, B + (size_t)(n0 + row) * K + ld_col);
        }
        CPA_COMMIT();
    }
    if (A32) {
        #pragma unroll
        for (int i = 0; i < 4; i++) {
            int row = ld_row0 + i * 32;
            uint32_t so = sb + (uint32_t)(row * APAD + ld_col) * 2 + A_OFF * 2;
            uint4 h;
            h.x = pack2(av[2 * i].x,     av[2 * i].y);
            h.y = pack2(av[2 * i].z,     av[2 * i].w);
            h.z = pack2(av[2 * i + 1].x, av[2 * i + 1].y);
            h.w = pack2(av[2 * i + 1].z, av[2 * i + 1].w);
            STS128(so, h);
        }
    }

    for (int it = 0; it < nit; ++it) {
        if (it + 1 < nit) {
            uint32_t base = sb + (uint32_t)(((it + 1) & 1) * STE) * 2;
            int k0 = (it + 1) << 6;
            if (A32) {
                #pragma unroll
                for (int i = 0; i < 4; i++) {
                    int row = ld_row0 + i * 32;
                    const float* ap = Af + (size_t)(m0 + row) * K + k0 + ld_col;
                    av[2 * i]     = *(const float4*)ap;
                    av[2 * i + 1] = *(const float4*)(ap + 4);
                }
            }
            #pragma unroll
            for (int i = 0; i < 4; i++) {
                int row = ld_row0 + i * 32;
                uint32_t so = base + (uint32_t)(row * APAD + ld_col) * 2;
                if (!A32)
                    cpa16(so + A_OFF * 2, A16 + (size_t)(m0 + row) * K + k0 + ld_col);
                cpa16(so + B_OFF * 2, B + (size_t)(n0 + row) * K + k0 + ld_col);
            }
            CPA_COMMIT();
            CPA_WAIT(1);
        } else {
            CPA_WAIT(0);
        }
        __syncthreads();

        uint32_t base = sb + (uint32_t)((it & 1) * STE) * 2;
        #pragma unroll
        for (int kk = 0; kk < 64; kk += 16) {
            uint32_t ah[2][4];
            #pragma unroll
            for (int mt = 0; mt < 2; mt++) {
                uint32_t ad = base + (uint32_t)((wm * 32 + mt * 16 + a_ld_row) * APAD + kk + a_ld_k) * 2;
                LDSM4(ah[mt][0], ah[mt][1], ah[mt][2], ah[mt][3], ad + A_OFF * 2);
            }
            #pragma unroll
            for (int np = 0; np < 4; np++) {
                uint32_t bh[4];
                uint32_t bd = base + (uint32_t)((wn * 64 + np * 16 + b_ld_row) * APAD + kk + b_ld_k) * 2;
                LDSM4(bh[0], bh[1], bh[2], bh[3], bd + B_OFF * 2);
                #pragma unroll
                for (int mt = 0; mt < 2; mt++) {
                    MMAF16(c[mt][np * 2 + 0], ah[mt], bh[0], bh[1]);
                    MMAF16(c[mt][np * 2 + 1], ah[mt], bh[2], bh[3]);
                }
            }
        }

        if (A32 && it + 1 < nit) {
            uint32_t base2 = sb + (uint32_t)(((it + 1) & 1) * STE) * 2;
            #pragma unroll
            for (int i = 0; i < 4; i++) {
                int row = ld_row0 + i * 32;
                uint32_t so = base2 + (uint32_t)(row * APAD + ld_col) * 2 + A_OFF * 2;
                uint4 h;
                h.x = pack2(av[2 * i].x,     av[2 * i].y);
                h.y = pack2(av[2 * i].z,     av[2 * i].w);
                h.z = pack2(av[2 * i + 1].x, av[2 * i + 1].y);
                h.w = pack2(av[2 * i + 1].z, av[2 * i + 1].w);
                STS128(so, h);
            }
        }
        __syncthreads();
    }

    #pragma unroll
    for (int mt = 0; mt < 2; mt++) {
        int row = m0 + wm * 32 + mt * 16 + (lane >> 2);
        #pragma unroll
        for (int nt = 0; nt < 8; nt++) {
            int col = n0 + wn * 64 + nt * 8 + (lane & 3) * 2;
            float2 bv = *(const float2*)(bias + col);
            float x0 = c[mt][nt][0] + bv.x, y0 = c[mt][nt][1] + bv.y;
            float x1 = c[mt][nt][2] + bv.x, y1 = c[mt][nt][3] + bv.y;
            if (OUT_HALF) {
                __half* C = (__half*)Cv;
                *(uint32_t*)(C + (size_t)row * N + col) = pack2(x0, y0);
                *(uint32_t*)(C + (size_t)(row + 8) * N + col) = pack2(x1, y1);
            } else {
                float* C = (float*)Cv;
                float2 v0; v0.x = x0; v0.y = y0;
                float2 v1; v1.x = x1; v1.y = y1;
                *(float2*)(C + (size_t)row * N + col) = v0;
                *(float2*)(C + (size_t)(row + 8) * N + col) = v1;
            }
        }
    }
}

__global__ __launch_bounds__(256, 2)
void gemm_qkv(const float* __restrict__ query, const float* __restrict__ key,
              const float* __restrict__ value,
              const __half* __restrict__ wq, const __half* __restrict__ wk,
              const __half* __restrict__ wv,
              const float* __restrict__ bqp, const float* __restrict__ bkp, const float* __restrict__ bv,
              __half* __restrict__ qp, __half* __restrict__ kp, __half* __restrict__ vp)
{
    extern __shared__ __half sm[];
    uint32_t sb = smem_u32(sm);
    const int m0 = blockIdx.y * 128;
    const int rr = blockIdx.x;
    if (rr < 3)
        gemm_tile128<true, true>(query, wq, bqp, qp, m0, rr * 128, NQKP, DMODEL, sb);
    else if (rr < 6)
        gemm_tile128<true, true>(key, wk, bkp, kp, m0, (rr - 3) * 128, NQKP, DMODEL, sb);
    else
        gemm_tile128<true, true>(value, wv, bv, vp, m0, (rr - 6) * 128, NV, DMODEL, sb);
}

__global__ __launch_bounds__(256, 2)
void gemm_out(const __half* __restrict__ A, const __half* __restrict__ B,
              const float* __restrict__ bias, float* __restrict__ C)
{
    extern __shared__ __half sm[];
    uint32_t sb = smem_u32(sm);
    gemm_tile128<false, false>(A, B, bias, C, blockIdx.y * 128, blockIdx.x * 128, DMODEL, NV, sb);
}

// ---------------- scores: 64-row tiles, merged all-subhead launch -------------
// smem: swin[(31*DIL+64)*64 half] | sq[2048 half]
template <int DILT, bool DYN>
__device__ __forceinline__ void scores_body(
    const __half* __restrict__ qp, const __half* __restrict__ kp,
    __half* __restrict__ sc, int s, int dil_rt)
{
    const int DIL = DYN ? dil_rt : DILT;
    const int WIN = 31 * DIL + 64;
    extern __shared__ __half sh[];
    __half* swin = sh;
    __half* sq   = swin + WIN * 64;

    const int l0 = blockIdx.x * 64;
    const int b  = blockIdx.y;
    const int tid = threadIdx.x, lane = tid & 31;
    const int w0 = l0 - 16 * DIL;
    const long rowbase = (long)b * L_SZ + l0;
    const int c8 = (tid & 7) * 8;

    // K window (64-row union)
    for (int r = tid >> 3; r < WIN; r += 32) {
        int g = w0 + r; g = g < 0 ? 0 : (g > L_SZ - 1 ? L_SZ - 1 : g);
        *(uint4*)(swin + r * 64 + c8) =
            *(const uint4*)(kp + ((long)b * L_SZ + g) * NQKP + s * 64 + c8);
    }

    #pragma unroll
    for (int sub = 0; sub < 2; sub++) {
        const int lo = sub * 32;
        // load Q sub-tile
        {
            int row = tid >> 3;
            *(uint4*)(sq + row * 64 + c8) =
                *(const uint4*)(qp + (rowbase + lo + row) * NQKP + s * 64 + c8);
        }
        __syncthreads();
        {
            const int li = tid >> 3;
            const int kb = (tid & 7) * 4;
            float acc0 = 0.f, acc1 = 0.f, acc2 = 0.f, acc3 = 0.f;
            const __half* qrow = sq + li * 64;
            const __half* wr0 = swin + (lo + li + (kb + 0) * DIL) * 64;
            const __half* wr1 = swin + (lo + li + (kb + 1) * DIL) * 64;
            const __half* wr2 = swin + (lo + li + (kb + 2) * DIL) * 64;
            const __half* wr3 = swin + (lo + li + (kb + 3) * DIL) * 64;
            #pragma unroll
            for (int t8 = 0; t8 < 8; t8++) {
                int i = ((t8 + lane) & 7) * 8;
                uint4 qr = *(const uint4*)(qrow + i);
                uint4 r0 = *(const uint4*)(wr0 + i);
                uint4 r1 = *(const uint4*)(wr1 + i);
                uint4 r2 = *(const uint4*)(wr2 + i);
                uint4 r3 = *(const uint4*)(wr3 + i);
                const __half2* qh = (const __half2*)&qr;
                const __half2* h0 = (const __half2*)&r0;
                const __half2* h1 = (const __half2*)&r1;
                const __half2* h2 = (const __half2*)&r2;
                const __half2* h3 = (const __half2*)&r3;
                #pragma unroll
                for (int u = 0; u < 4; u++) {
                    float2 qf = __half22float2(qh[u]);
                    float2 f0 = __half22float2(h0[u]);
                    float2 f1 = __half22float2(h1[u]);
                    float2 f2 = __half22float2(h2[u]);
                    float2 f3 = __half22float2(h3[u]);
                    acc0 += qf.x * f0.x + qf.y * f0.y;
                    acc1 += qf.x * f1.x + qf.y * f1.y;
                    acc2 += qf.x * f2.x + qf.y * f2.y;
                    acc3 += qf.x * f3.x + qf.y * f3.y;
                }
            }
            uint2 o;
            o.x = pack2(acc0 * 0.125f, acc1 * 0.125f);
            o.y = pack2(acc2 * 0.125f, acc3 * 0.125f);
            *(uint2*)(sc + (((size_t)s * B_SZ + b) * L_SZ + l0 + lo + li) * KW + kb) = o;
        }
        if (sub == 0) __syncthreads();   // protect sq reuse
    }
}

__global__ __launch_bounds__(256)
void scores_all(const __half* __restrict__ qp, const __half* __restrict__ kp, __half* __restrict__ sc)
{
    const int z = blockIdx.z;
    if (z < 2) {
        scores_body<1, false>(qp, kp, sc, z, 1);
    } else {
        const int dil = (z == 2) ? 2 : (z == 3 ? 4 : 8);
        scores_body<0, true>(qp, kp, sc, z, dil);
    }
}

// ---------------- head kernel: 64-row tiles ------------------------------------
// smem: swin[(31*DIL+64)*64 half] | sws_h[1024 half] | ssc[1152 f] | ssm[1056 f] | satt[1024 f] | sbs[32 f]
#define HEAD_FIXED_B (1024 * 2 + (1152 + 1056 + 1024 + 32) * 4)

template <int DILT, bool DYN>
__device__ __forceinline__ void head_body(
    const __half* __restrict__ vp, const __half* __restrict__ sc_g,
    const float* __restrict__ Ws, const float* __restrict__ bsg,
    __half* __restrict__ oa, int h, int s, int dil_rt)
{
    const int DIL = DYN ? dil_rt : DILT;
    const int WIN = 31 * DIL + 64;
    extern __shared__ char sab[];
    __half* swin  = (__half*)sab;
    __half* sws_h = (__half*)(sab + (size_t)WIN * 128);
    float* ssc  = (float*)(sws_h + 1024);
    float* ssm  = ssc + 1152;
    float* satt = ssm + 1056;
    float* sbs  = satt + 1024;

    const int l0 = blockIdx.x * 64;
    const int b  = blockIdx.y;
    const int tid = threadIdx.x, lane = tid & 31;
    const int w0 = l0 - 16 * DIL;
    const long rowbase = (long)b * L_SZ + l0;

    // Ws (fp32->fp16), bs, V window (64-row union)
    {
        float4 wv4 = *(const float4*)(Ws + (size_t)h * 1024 + tid * 4);
        uint2 wp;
        wp.x = pack2(wv4.x, wv4.y);
        wp.y = pack2(wv4.z, wv4.w);
        *(uint2*)(sws_h + tid * 4) = wp;
    }
    if (tid < 32) sbs[tid] = bsg[h * KW + tid];
    for (int r = tid >> 3; r < WIN; r += 32) {
        int g = w0 + r; g = g < 0 ? 0 : (g > L_SZ - 1 ? L_SZ - 1 : g);
        int c8 = (tid & 7) * 8;
        *(uint4*)(swin + r * 64 + c8) =
            *(const uint4*)(vp + ((long)b * L_SZ + g) * NV + h * 64 + c8);
    }

    #pragma unroll
    for (int sub = 0; sub < 2; sub++) {
        const int lo = sub * 32;
        // load sc sub-tile
        {
            int li = tid >> 3, kb = (tid & 7) * 4;
            uint2 raw = *(const uint2*)(sc_g + (((size_t)s * B_SZ + b) * L_SZ + l0 + lo + li) * KW + kb);
            float2 f0 = __half22float2(*(__half2*)&raw.x);
            float2 f1 = __half22float2(*(__half2*)&raw.y);
            ssc[li * 36 + kb + 0] = f0.x;
            ssc[li * 36 + kb + 1] = f0.y;
            ssc[li * 36 + kb + 2] = f1.x;
            ssc[li * 36 + kb + 3] = f1.y;
        }
        __syncthreads();

        // resample (fp16 Ws)
        {
            const int li = tid >> 3;
            const int m4 = (tid & 7) * 4;
            float a0 = sbs[m4], a1 = sbs[m4 + 1], a2 = sbs[m4 + 2], a3 = sbs[m4 + 3];
            #pragma unroll 8
            for (int k = 0; k < 32; k++) {
                float scv = ssc[li * 36 + k];
                uint2 raw = *(const uint2*)(sws_h + k * 32 + m4);
                float2 w0f = __half22float2(*(__half2*)&raw.x);
                float2 w1f = __half22float2(*(__half2*)&raw.y);
                a0 += scv * w0f.x; a1 += scv * w0f.y; a2 += scv * w1f.x; a3 += scv * w1f.y;
            }
            ssm[li * 33 + m4 + 0] = a0;
            ssm[li * 33 + m4 + 1] = a1;
            ssm[li * 33 + m4 + 2] = a2;
            ssm[li * 33 + m4 + 3] = a3;
        }
        __syncthreads();

        // softmax
        {
            const int w = tid >> 5;
            #pragma unroll
            for (int rr = 0; rr < 4; rr++) {
                int li = w * 4 + rr;
                float v = ssm[li * 33 + lane];
                float mx = v;
                #pragma unroll
                for (int o = 16; o; o >>= 1) mx = fmaxf(mx, __shfl_xor_sync(0xffffffffu, mx, o));
                float e = __expf(v - mx);
                float ss = e;
                #pragma unroll
                for (int o = 16; o; o >>= 1) ss += __shfl_xor_sync(0xffffffffu, ss, o);
                satt[li * 32 + lane] = e / ss;
            }
        }
        __syncthreads();

        if (!DYN && DILT == 1) {
            // row-centric AV (d=1), fully unrolled
            const int w = tid >> 5;
            const int li0 = w * 4;
            float2 acc[4];
            #pragma unroll
            for (int q = 0; q < 4; q++) { acc[q].x = 0.f; acc[q].y = 0.f; }
            #pragma unroll
            for (int rr = 0; rr < 35; rr++) {
                int row = lo + li0 + rr;
                __half2 vh = *(const __half2*)(swin + row * 64 + lane * 2);
                float2 vf = __half22float2(vh);
                #pragma unroll
                for (int q = 0; q < 4; q++) {
                    int k = rr - q;
                    if (k >= 0 && k < 32) {
                        float a = satt[(li0 + q) * 32 + k];
                        acc[q].x += a * vf.x;
                        acc[q].y += a * vf.y;
                    }
                }
            }
            #pragma unroll
            for (int q = 0; q < 4; q++)
                *(uint32_t*)(oa + (rowbase + lo + li0 + q) * NV + h * 64 + lane * 2) =
                    pack2(acc[q].x, acc[q].y);
        } else {
            const int li = tid >> 3;
            const int io = (tid & 7) * 8;
            float4 a0 = make_float4(0.f, 0.f, 0.f, 0.f);
            float4 a1 = make_float4(0.f, 0.f, 0.f, 0.f);
            #pragma unroll 8
            for (int k = 0; k < 32; k++) {
                float wv = satt[li * 32 + k];
                const __half* vr = swin + (lo + li + k * DIL) * 64 + io;
                uint4 raw = *(const uint4*)vr;
                const __half2* hp = (const __half2*)&raw;
                float2 f0 = __half22float2(hp[0]);
                float2 f1 = __half22float2(hp[1]);
                float2 f2 = __half22float2(hp[2]);
                float2 f3 = __half22float2(hp[3]);
                a0.x += wv * f0.x; a0.y += wv * f0.y; a0.z += wv * f1.x; a0.w += wv * f1.y;
                a1.x += wv * f2.x; a1.y += wv * f2.y; a1.z += wv * f3.x; a1.w += wv * f3.y;
            }
            uint4 hv;
            hv.x = pack2(a0.x, a0.y);
            hv.y = pack2(a0.z, a0.w);
            hv.z = pack2(a1.x, a1.y);
            hv.w = pack2(a1.z, a1.w);
            *(uint4*)(oa + (rowbase + lo + li) * NV + h * 64 + io) = hv;
        }
        if (sub == 0) __syncthreads();   // protect ssc/ssm/satt reuse
    }
}

__global__ __launch_bounds__(256)
void head_d1(const __half* __restrict__ vp, const __half* __restrict__ sc,
             const float* __restrict__ Ws, const float* __restrict__ bsg,
             __half* __restrict__ oa)
{
    const int h = blockIdx.z;
    head_body<1, false>(vp, sc, Ws, bsg, oa, h, (h < 5) ? 0 : 1, 1);
}
__global__ __launch_bounds__(256)
void head_dyn(const __half* __restrict__ vp, const __half* __restrict__ sc,
              const float* __restrict__ Ws, const float* __restrict__ bsg,
              __half* __restrict__ oa)
{
    const int z = blockIdx.z;
    const int h = 10 + z;
    const int s = (h < 12) ? 2 : (h == 12 ? 3 : 4);
    const int dil = (h < 12) ? 2 : (h == 12 ? 4 : 8);
    head_body<0, true>(vp, sc, Ws, bsg, oa, h, s, dil);
}

// ---------------- launcher ---------------------------------------------------
extern "C" void kernel_launch(void* const* d_in, const int* in_sizes, int n_in,
                              void* d_out, int out_size)
{
    const float* query = (const float*)d_in[0];
    const float* key   = (const float*)d_in[1];
    const float* value = (const float*)d_in[2];
    const float* Wq    = (const float*)d_in[3];
    const float* bq    = (const float*)d_in[4];
    const float* Wk    = (const float*)d_in[5];
    const float* bk    = (const float*)d_in[6];
    const float* Wv    = (const float*)d_in[7];
    const float* bv    = (const float*)d_in[8];
    const float* Ws    = (const float*)d_in[9];
    const float* bs    = (const float*)d_in[10];
    const float* Wc    = (const float*)d_in[11];
    const float* bc    = (const float*)d_in[12];
    float* out = (float*)d_out;

    float *bqp, *bkp;
    __half *qp, *kp, *vp, *sc, *oa, *wq, *wk, *wv, *wc;
    cudaGetSymbolAddress((void**)&qp, g_qp);
    cudaGetSymbolAddress((void**)&kp, g_kp);
    cudaGetSymbolAddress((void**)&vp, g_vp);
    cudaGetSymbolAddress((void**)&sc, g_sc);
    cudaGetSymbolAddress((void**)&bqp, g_bqp);
    cudaGetSymbolAddress((void**)&bkp, g_bkp);
    cudaGetSymbolAddress((void**)&oa, g_oa);
    cudaGetSymbolAddress((void**)&wq, g_wq);
    cudaGetSymbolAddress((void**)&wk, g_wk);
    cudaGetSymbolAddress((void**)&wv, g_wv);
    cudaGetSymbolAddress((void**)&wc, g_wc);

    cudaFuncSetAttribute(gemm_qkv, cudaFuncAttributeMaxDynamicSharedMemorySize, GEMM_SMEM);
    cudaFuncSetAttribute(gemm_out, cudaFuncAttributeMaxDynamicSharedMemorySize, GEMM_SMEM);

    auto ssz = [](int dil) { return (size_t)((31 * dil + 64) * 64 + 2048) * 2; };
    auto hsz = [](int dil) { return (size_t)(31 * dil + 64) * 128 + (size_t)HEAD_FIXED_B; };
    cudaFuncSetAttribute(scores_all, cudaFuncAttributeMaxDynamicSharedMemorySize, (int)ssz(8));
    cudaFuncSetAttribute(head_d1,    cudaFuncAttributeMaxDynamicSharedMemorySize, (int)hsz(1));
    cudaFuncSetAttribute(head_dyn,   cudaFuncAttributeMaxDynamicSharedMemorySize, (int)hsz(8));

    // ---- weight conversions only ----
    conv_w_all<<<CONV_BLOCKS, 256>>>(Wq, Wk, Wv, Wc, bq, bk, wq, wk, wv, wc, bqp, bkp);

    // ---- fused Q/K/V projection (reads fp32 activations directly) ----
    gemm_qkv<<<dim3(13, 64), 256, GEMM_SMEM>>>(query, key, value, wq, wk, wv,
                                               bqp, bkp, bv, qp, kp, vp);

    // ---- per-subhead scores (64-row tiles) ----
    scores_all<<<dim3(L_SZ / 64, B_SZ, SUBH), 256, ssz(8)>>>(qp, kp, sc);

    // ---- per-head resample + softmax + AV (64-row tiles) ----
    head_d1<<<dim3(L_SZ / 64, B_SZ, 10), 256, hsz(1)>>>(vp, sc, Ws, bs, oa);
    head_dyn<<<dim3(L_SZ / 64, B_SZ, 4), 256, hsz(8)>>>(vp, sc, Ws, bs, oa);

    // ---- output projection ----
    gemm_out<<<dim3(8, 64), 256, GEMM_SMEM>>>(oa, wc, bc, out);
}